// round 8
// baseline (speedup 1.0000x reference)
#include <cuda_runtime.h>
#include <math_constants.h>

#define N_PRE 8192
#define N_CUR 16384
#define KNN   8
#define NTHREADS 256

#define P1    32                  // partitions over pre (k1)
#define TILE1 (N_PRE / P1)        // 256
#define P2    32                  // partitions over cur (k2)
#define TILE2 (N_CUR / P2)        // 512
#define NCHUNK 128                // fine chunks over cur (128 wide)
#define CHUNK  (N_CUR / NCHUNK)   // 128
#define CAP   64
#define FWARPS 8
#define QB    4                   // queries per thread in min passes
#define K1BLK (N_CUR / (NTHREADS * QB) * P1)   // 16 * 32 = 512
#define K2BLK (N_PRE / (NTHREADS * QB) * P2)   // 8 * 32  = 256

// Scratch (device globals; no allocations allowed)
__device__ int    g_cur2pre[N_CUR];
__device__ float  g_p1_min[P1 * N_CUR];    // per-partition min key (cur->pre)
__device__ float  g_cmin[NCHUNK * N_PRE];  // per-128-chunk min key (pre->cur)
__device__ float  g_T[N_PRE];
__device__ float4 g_prep[N_PRE];           // packed pre: (x,y,z,|p|^2)
__device__ float4 g_curp[N_CUR];           // packed cur: (x,y,z,|c|^2)

// ---- packed f32x2 helpers ---------------------------------------------------
__device__ __forceinline__ unsigned long long packf2(float a, float b) {
    unsigned long long r;
    asm("mov.b64 %0, {%1,%2};" : "=l"(r) : "f"(a), "f"(b));
    return r;
}
__device__ __forceinline__ unsigned long long fma2(unsigned long long a,
                                                   unsigned long long b,
                                                   unsigned long long c) {
    unsigned long long d;
    asm("fma.rn.f32x2 %0, %1, %2, %3;" : "=l"(d) : "l"(a), "l"(b), "l"(c));
    return d;
}
__device__ __forceinline__ void unpackf2(unsigned long long v, float& lo, float& hi) {
    asm("mov.b64 {%0,%1}, %2;" : "=f"(lo), "=f"(hi) : "l"(v));
}

// key(q, c) = fmaf(m2z, cz, fmaf(m2y, cy, fmaf(m2x, cx, |c|^2))), m2* = -2*q*.
// Identical op order in packed (per-lane IEEE) and scalar recompute -> bitwise
// equal across kernels.

// ---------------------------------------------------------------------------
// Launch 1: merged index-free min passes, 4 queries per thread.
//  blocks [0, 512):   k1 — min over a 256-wide PRE tile for 1024 cur queries
//  blocks [512, 768): k2 — four 128-chunk minima over a 512-wide CUR tile for
//                     1024 pre queries
// ---------------------------------------------------------------------------
__global__ __launch_bounds__(NTHREADS)
void k_minpass(const float* __restrict__ pre, const float* __restrict__ cur) {
    __shared__ ulonglong2 tXY[256], tZN[256];
    const int tid = threadIdx.x;
    const int bid = blockIdx.x;

    if (bid < K1BLK) {
        // ---------------- k1: cur -> pre partition minima ----------------
        const int part = bid & (P1 - 1);
        const int yq   = bid >> 5;                    // 0..15
        const int base = part * TILE1;
        for (int p = tid; p < TILE1 / 2; p += NTHREADS) {
            int t0 = base + 2 * p, t1 = t0 + 1;
            float x0 = pre[t0],             x1 = pre[t1];
            float y0 = pre[N_PRE + t0],     y1 = pre[N_PRE + t1];
            float z0 = pre[2 * N_PRE + t0], z1 = pre[2 * N_PRE + t1];
            float n0 = fmaf(z0, z0, fmaf(y0, y0, x0 * x0));
            float n1 = fmaf(z1, z1, fmaf(y1, y1, x1 * x1));
            tXY[p] = make_ulonglong2(packf2(x0, x1), packf2(y0, y1));
            tZN[p] = make_ulonglong2(packf2(z0, z1), packf2(n0, n1));
            if (yq == 0) {
                g_prep[t0] = make_float4(x0, y0, z0, n0);
                g_prep[t1] = make_float4(x1, y1, z1, n1);
            }
        }
        __syncthreads();

        int j[QB];
        unsigned long long cx[QB], cy[QB], cz[QB];
#pragma unroll
        for (int q = 0; q < QB; ++q) {
            j[q] = yq * (NTHREADS * QB) + q * NTHREADS + tid;
            float vx = -2.0f * cur[j[q]];
            float vy = -2.0f * cur[N_CUR + j[q]];
            float vz = -2.0f * cur[2 * N_CUR + j[q]];
            cx[q] = packf2(vx, vx); cy[q] = packf2(vy, vy); cz[q] = packf2(vz, vz);
        }

        float m0[QB], m1[QB];
#pragma unroll
        for (int q = 0; q < QB; ++q) { m0[q] = CUDART_INF_F; m1[q] = CUDART_INF_F; }

#pragma unroll 8
        for (int p = 0; p < TILE1 / 2; ++p) {
            ulonglong2 xy = tXY[p], zn = tZN[p];
#pragma unroll
            for (int q = 0; q < QB; ++q) {
                unsigned long long k = fma2(cz[q], zn.x, fma2(cy[q], xy.y, fma2(cx[q], xy.x, zn.y)));
                float lo, hi;
                unpackf2(k, lo, hi);
                m0[q] = fminf(m0[q], lo);
                m1[q] = fminf(m1[q], hi);
            }
        }
#pragma unroll
        for (int q = 0; q < QB; ++q)
            g_p1_min[part * N_CUR + j[q]] = fminf(m0[q], m1[q]);
    } else {
        // ---------------- k2: pre -> cur 128-chunk minima ----------------
        const int b    = bid - K1BLK;
        const int part = b & (P2 - 1);
        const int yq   = b >> 5;                      // 0..7
        const int base = part * TILE2;
        for (int p = tid; p < TILE2 / 2; p += NTHREADS) {
            int t0 = base + 2 * p, t1 = t0 + 1;
            float x0 = cur[t0],             x1 = cur[t1];
            float y0 = cur[N_CUR + t0],     y1 = cur[N_CUR + t1];
            float z0 = cur[2 * N_CUR + t0], z1 = cur[2 * N_CUR + t1];
            float n0 = fmaf(z0, z0, fmaf(y0, y0, x0 * x0));
            float n1 = fmaf(z1, z1, fmaf(y1, y1, x1 * x1));
            tXY[p] = make_ulonglong2(packf2(x0, x1), packf2(y0, y1));
            tZN[p] = make_ulonglong2(packf2(z0, z1), packf2(n0, n1));
            if (yq == 0) {
                g_curp[t0] = make_float4(x0, y0, z0, n0);
                g_curp[t1] = make_float4(x1, y1, z1, n1);
            }
        }
        __syncthreads();

        int i[QB];
        unsigned long long cx[QB], cy[QB], cz[QB];
#pragma unroll
        for (int q = 0; q < QB; ++q) {
            i[q] = yq * (NTHREADS * QB) + q * NTHREADS + tid;
            float vx = -2.0f * pre[i[q]];
            float vy = -2.0f * pre[N_PRE + i[q]];
            float vz = -2.0f * pre[2 * N_PRE + i[q]];
            cx[q] = packf2(vx, vx); cy[q] = packf2(vy, vy); cz[q] = packf2(vz, vz);
        }

#pragma unroll
        for (int c = 0; c < 4; ++c) {                 // 4 chunks of 128
            float m0[QB], m1[QB];
#pragma unroll
            for (int q = 0; q < QB; ++q) { m0[q] = CUDART_INF_F; m1[q] = CUDART_INF_F; }
#pragma unroll 8
            for (int p = c * 64; p < (c + 1) * 64; ++p) {
                ulonglong2 xy = tXY[p], zn = tZN[p];
#pragma unroll
                for (int q = 0; q < QB; ++q) {
                    unsigned long long k = fma2(cz[q], zn.x, fma2(cy[q], xy.y, fma2(cx[q], xy.x, zn.y)));
                    float lo, hi;
                    unpackf2(k, lo, hi);
                    m0[q] = fminf(m0[q], lo);
                    m1[q] = fminf(m1[q], hi);
                }
            }
            const int ch = part * 4 + c;
#pragma unroll
            for (int q = 0; q < QB; ++q)
                g_cmin[ch * N_PRE + i[q]] = fminf(m0[q], m1[q]);
        }
    }
}

// ---------------------------------------------------------------------------
// Launch 2 (combo, warp-per-query):
//  blocks [0, 2048):  k1 argmin recovery — min over 32 partition minima, owner
//    = lowest partition with pmin==gmin, rescan its 256-wide tile for the first
//    bitwise-equal key -> g_cur2pre (== argmin lowest-index tie rule).
//  blocks [2048, 3072): T = 8th-smallest of 128 chunk minima (exact superset).
// ---------------------------------------------------------------------------
__global__ __launch_bounds__(NTHREADS)
void k_combo(const float* __restrict__ pre, const float* __restrict__ cur) {
    const int w    = threadIdx.x >> 5;
    const int lane = threadIdx.x & 31;

    if (blockIdx.x < N_CUR / FWARPS) {
        const int j = blockIdx.x * FWARPS + w;          // cur query
        const float pm = g_p1_min[lane * N_CUR + j];
        float gm = pm;
#pragma unroll
        for (int off = 16; off > 0; off >>= 1)
            gm = fminf(gm, __shfl_xor_sync(0xFFFFFFFFu, gm, off));
        const unsigned owners = __ballot_sync(0xFFFFFFFFu, pm == gm);
        const int opart = __ffs(owners) - 1;

        const float m2x = -2.0f * cur[j];
        const float m2y = -2.0f * cur[N_CUR + j];
        const float m2z = -2.0f * cur[2 * N_CUR + j];
        const int base = opart * TILE1;
        int found = -1;
#pragma unroll
        for (int t = 0; t < TILE1; t += 32) {
            if (found >= 0) break;                      // uniform
            const float4 c = g_prep[base + t + lane];
            const float key = fmaf(m2z, c.z, fmaf(m2y, c.y, fmaf(m2x, c.x, c.w)));
            unsigned m = __ballot_sync(0xFFFFFFFFu, key == gm);
            if (m) found = base + t + (__ffs(m) - 1);
        }
        if (lane == 0) g_cur2pre[j] = found;
    } else {
        const int i = (blockIdx.x - N_CUR / FWARPS) * FWARPS + w;   // pre query
        float v0 = g_cmin[lane * N_PRE + i];
        float v1 = g_cmin[(lane + 32) * N_PRE + i];
        float v2 = g_cmin[(lane + 64) * N_PRE + i];
        float v3 = g_cmin[(lane + 96) * N_PRE + i];
        float T = 0.0f;
#pragma unroll
        for (int r = 0; r < KNN; ++r) {
            float lmin = fminf(fminf(v0, v1), fminf(v2, v3));
            float gm = lmin;
#pragma unroll
            for (int off = 16; off > 0; off >>= 1)
                gm = fminf(gm, __shfl_xor_sync(0xFFFFFFFFu, gm, off));
            T = gm;
            const unsigned own = __ballot_sync(0xFFFFFFFFu, lmin == gm);
            if (lane == __ffs(own) - 1) {               // remove ONE instance
                if      (v0 == gm) v0 = CUDART_INF_F;
                else if (v1 == gm) v1 = CUDART_INF_F;
                else if (v2 == gm) v2 = CUDART_INF_F;
                else               v3 = CUDART_INF_F;
            }
        }
        if (lane == 0) g_T[i] = T;
    }
}

// ---------------------------------------------------------------------------
// Launch 3: filter + final, warp per pre query. Scan ONLY chunks with min<=T
// (generically exactly 8 of 128 -> 1024 candidates); admit key<=T via
// ballot/popc into smem; exact top-8 via lexicographic warp-argmin; epilogue.
// ---------------------------------------------------------------------------
__global__ __launch_bounds__(NTHREADS)
void k_filter_final(const float* __restrict__ pre, const float* __restrict__ ups,
                    float* __restrict__ out) {
    __shared__ float sk[FWARPS][CAP];
    __shared__ int   si[FWARPS][CAP];
    const int w    = threadIdx.x >> 5;
    const int lane = threadIdx.x & 31;
    const int i    = blockIdx.x * FWARPS + w;

    const float m2x = -2.0f * pre[i];
    const float m2y = -2.0f * pre[N_PRE + i];
    const float m2z = -2.0f * pre[2 * N_PRE + i];
    const float T   = g_T[i];

    unsigned cm[4];
#pragma unroll
    for (int s = 0; s < 4; ++s) {
        const float q = g_cmin[(s * 32 + lane) * N_PRE + i];
        cm[s] = __ballot_sync(0xFFFFFFFFu, q <= T);
    }

    int cnt = 0;
#pragma unroll
    for (int s = 0; s < 4; ++s) {
        unsigned msk = cm[s];
        while (msk) {
            const int p = __ffs(msk) - 1;
            msk &= msk - 1;
            const int base = (s * 32 + p) * CHUNK;
#pragma unroll
            for (int t = 0; t < CHUNK; t += 32) {
                const float4 c = g_curp[base + t + lane];
                const float key = fmaf(m2z, c.z, fmaf(m2y, c.y, fmaf(m2x, c.x, c.w)));
                const bool adm = (key <= T);
                unsigned m = __ballot_sync(0xFFFFFFFFu, adm);
                if (m) {
                    int pos = cnt + __popc(m & ((1u << lane) - 1u));
                    if (adm && pos < CAP) { sk[w][pos] = key; si[w][pos] = base + t + lane; }
                    cnt += __popc(m);
                }
            }
        }
    }
    cnt = min(cnt, CAP);

    float c0 = (lane < cnt)      ? sk[w][lane]      : CUDART_INF_F;
    int   x0 = (lane < cnt)      ? si[w][lane]      : 0x7FFFFFFF;
    float c1 = (lane + 32 < cnt) ? sk[w][lane + 32] : CUDART_INF_F;
    int   x1 = (lane + 32 < cnt) ? si[w][lane + 32] : 0x7FFFFFFF;

    int   sel  = 0;
    float selk = CUDART_INF_F;
#pragma unroll
    for (int r = 0; r < KNN; ++r) {
        float mk = c0; int mi = x0;
        if (c1 < mk || (c1 == mk && x1 < mi)) { mk = c1; mi = x1; }
#pragma unroll
        for (int off = 16; off > 0; off >>= 1) {
            float ok = __shfl_down_sync(0xFFFFFFFFu, mk, off);
            int   oi = __shfl_down_sync(0xFFFFFFFFu, mi, off);
            if (ok < mk || (ok == mk && oi < mi)) { mk = ok; mi = oi; }
        }
        const int   wi = __shfl_sync(0xFFFFFFFFu, mi, 0);
        const float wk = __shfl_sync(0xFFFFFFFFu, mk, 0);
        if (lane == r) { sel = wi; selk = wk; }
        if (x0 == wi) c0 = CUDART_INF_F;
        if (x1 == wi) c1 = CUDART_INF_F;
    }

    const float px = pre[i];
    const float py = pre[N_PRE + i];
    const float pz = pre[2 * N_PRE + i];

    float val = 0.0f;
    if (lane < KNN && selk < CUDART_INF_F) {
        const int j = sel;
        const float4 c = g_curp[j];
        float dx = c.x - px, dy = c.y - py, dz = c.z - pz;
        float dist = sqrtf(fmaf(dz, dz, fmaf(dy, dy, dx * dx)));
        val = (g_cur2pre[j] == i) ? dist : 0.0f;
    }
#pragma unroll
    for (int off = 4; off > 0; off >>= 1)
        val += __shfl_down_sync(0xFFFFFFFFu, val, off);

    if (lane == 0) out[i] = val / ups[i];
}

// ---------------------------------------------------------------------------
extern "C" void kernel_launch(void* const* d_in, const int* in_sizes, int n_in,
                              void* d_out, int out_size) {
    const float* pre = (const float*)d_in[0];   // (1, 3, 8192)
    const float* cur = (const float*)d_in[1];   // (1, 3, 16384)
    const float* ups = (const float*)d_in[2];   // (1, 8192)
    float* out = (float*)d_out;                 // (1, 8192)

    k_minpass<<<K1BLK + K2BLK, NTHREADS>>>(pre, cur);          // 768 blocks

    k_combo<<<N_CUR / FWARPS + N_PRE / FWARPS, NTHREADS>>>(pre, cur);

    k_filter_final<<<N_PRE / FWARPS, NTHREADS>>>(pre, ups, out);
}

// round 10
// speedup vs baseline: 1.1095x; 1.1095x over previous
#include <cuda_runtime.h>
#include <math_constants.h>

#define N_PRE 8192
#define N_CUR 16384
#define KNN   8
#define NTHREADS 256

#define P1    32                  // partitions over pre (k1)
#define TILE1 (N_PRE / P1)        // 256
#define P2    64                  // partitions over cur (k2), 256 wide
#define TILE2 (N_CUR / P2)        // 256
#define NCHUNK 128                // fine chunks over cur (128 wide)
#define CHUNK  (N_CUR / NCHUNK)   // 128
#define CAP   64
#define FWARPS 8
#define K1BLK (P1 * (N_CUR / 512))   // 32*32 = 1024
#define K2BLK (P2 * (N_PRE / 512))   // 64*16 = 1024

// Scratch (device globals; no allocations allowed)
__device__ int    g_cur2pre[N_CUR];
__device__ float  g_p1_min[P1 * N_CUR];    // per-partition min key (cur->pre)
__device__ float  g_cmin[NCHUNK * N_PRE];  // per-128-chunk min key (pre->cur)
__device__ float  g_T[N_PRE];
__device__ float4 g_prep[N_PRE];           // packed pre: (x,y,z,|p|^2)
__device__ float4 g_curp[N_CUR];           // packed cur: (x,y,z,|c|^2)

// ---- packed f32x2 helpers ---------------------------------------------------
__device__ __forceinline__ unsigned long long packf2(float a, float b) {
    unsigned long long r;
    asm("mov.b64 %0, {%1,%2};" : "=l"(r) : "f"(a), "f"(b));
    return r;
}
__device__ __forceinline__ unsigned long long fma2(unsigned long long a,
                                                   unsigned long long b,
                                                   unsigned long long c) {
    unsigned long long d;
    asm("fma.rn.f32x2 %0, %1, %2, %3;" : "=l"(d) : "l"(a), "l"(b), "l"(c));
    return d;
}
__device__ __forceinline__ void unpackf2(unsigned long long v, float& lo, float& hi) {
    asm("mov.b64 {%0,%1}, %2;" : "=f"(lo), "=f"(hi) : "l"(v));
}

// key(q, c) = fmaf(m2z, cz, fmaf(m2y, cy, fmaf(m2x, cx, |c|^2))), m2* = -2*q*.
// Per-lane IEEE fma order identical in packed and scalar recompute -> bitwise
// equal across kernels.

// ---------------------------------------------------------------------------
// Launch 1: merged index-free min passes. 2048 uniform blocks, 128-iter loops.
//  blocks [0, 1024):    k1 — min over a 256-wide PRE tile for 512 cur queries
//  blocks [1024, 2048): k2 — two 128-chunk minima over a 256-wide CUR tile for
//                       512 pre queries
// ---------------------------------------------------------------------------
__global__ __launch_bounds__(NTHREADS)
void k_minpass(const float* __restrict__ pre, const float* __restrict__ cur) {
    __shared__ ulonglong2 tXY[128], tZN[128];
    const int tid = threadIdx.x;
    const int bid = blockIdx.x;

    if (bid < K1BLK) {
        // ---------------- k1: cur -> pre partition minima ----------------
        const int part = bid & (P1 - 1);
        const int yq   = bid >> 5;                    // 0..31
        const int base = part * TILE1;
        if (tid < TILE1 / 2) {
            int t0 = base + 2 * tid, t1 = t0 + 1;
            float x0 = pre[t0],             x1 = pre[t1];
            float y0 = pre[N_PRE + t0],     y1 = pre[N_PRE + t1];
            float z0 = pre[2 * N_PRE + t0], z1 = pre[2 * N_PRE + t1];
            float n0 = fmaf(z0, z0, fmaf(y0, y0, x0 * x0));
            float n1 = fmaf(z1, z1, fmaf(y1, y1, x1 * x1));
            tXY[tid] = make_ulonglong2(packf2(x0, x1), packf2(y0, y1));
            tZN[tid] = make_ulonglong2(packf2(z0, z1), packf2(n0, n1));
            if (yq == 0) {
                g_prep[t0] = make_float4(x0, y0, z0, n0);
                g_prep[t1] = make_float4(x1, y1, z1, n1);
            }
        }
        __syncthreads();

        const int j0 = yq * 512 + tid;
        const int j1 = j0 + NTHREADS;
        float vax = -2.0f * cur[j0], vay = -2.0f * cur[N_CUR + j0], vaz = -2.0f * cur[2 * N_CUR + j0];
        float vbx = -2.0f * cur[j1], vby = -2.0f * cur[N_CUR + j1], vbz = -2.0f * cur[2 * N_CUR + j1];
        const unsigned long long ax = packf2(vax, vax), ay = packf2(vay, vay), az = packf2(vaz, vaz);
        const unsigned long long bx = packf2(vbx, vbx), by = packf2(vby, vby), bz = packf2(vbz, vbz);

        float ma0 = CUDART_INF_F, ma1 = CUDART_INF_F;
        float mb0 = CUDART_INF_F, mb1 = CUDART_INF_F;
#pragma unroll 8
        for (int p = 0; p < TILE1 / 2; ++p) {
            ulonglong2 xy = tXY[p], zn = tZN[p];
            unsigned long long kA = fma2(az, zn.x, fma2(ay, xy.y, fma2(ax, xy.x, zn.y)));
            unsigned long long kB = fma2(bz, zn.x, fma2(by, xy.y, fma2(bx, xy.x, zn.y)));
            float lo, hi;
            unpackf2(kA, lo, hi); ma0 = fminf(ma0, lo); ma1 = fminf(ma1, hi);
            unpackf2(kB, lo, hi); mb0 = fminf(mb0, lo); mb1 = fminf(mb1, hi);
        }
        g_p1_min[part * N_CUR + j0] = fminf(ma0, ma1);
        g_p1_min[part * N_CUR + j1] = fminf(mb0, mb1);
    } else {
        // ---------------- k2: pre -> cur 128-chunk minima ----------------
        const int b    = bid - K1BLK;
        const int part = b & (P2 - 1);
        const int yq   = b >> 6;                      // 0..15
        const int base = part * TILE2;
        if (tid < TILE2 / 2) {
            int t0 = base + 2 * tid, t1 = t0 + 1;
            float x0 = cur[t0],             x1 = cur[t1];
            float y0 = cur[N_CUR + t0],     y1 = cur[N_CUR + t1];
            float z0 = cur[2 * N_CUR + t0], z1 = cur[2 * N_CUR + t1];
            float n0 = fmaf(z0, z0, fmaf(y0, y0, x0 * x0));
            float n1 = fmaf(z1, z1, fmaf(y1, y1, x1 * x1));
            tXY[tid] = make_ulonglong2(packf2(x0, x1), packf2(y0, y1));
            tZN[tid] = make_ulonglong2(packf2(z0, z1), packf2(n0, n1));
            if (yq == 0) {
                g_curp[t0] = make_float4(x0, y0, z0, n0);
                g_curp[t1] = make_float4(x1, y1, z1, n1);
            }
        }
        __syncthreads();

        const int i0 = yq * 512 + tid;
        const int i1 = i0 + NTHREADS;
        float vax = -2.0f * pre[i0], vay = -2.0f * pre[N_PRE + i0], vaz = -2.0f * pre[2 * N_PRE + i0];
        float vbx = -2.0f * pre[i1], vby = -2.0f * pre[N_PRE + i1], vbz = -2.0f * pre[2 * N_PRE + i1];
        const unsigned long long ax = packf2(vax, vax), ay = packf2(vay, vay), az = packf2(vaz, vaz);
        const unsigned long long bx = packf2(vbx, vbx), by = packf2(vby, vby), bz = packf2(vbz, vbz);

#pragma unroll
        for (int c = 0; c < 2; ++c) {                 // 2 chunks of 128
            float ma0 = CUDART_INF_F, ma1 = CUDART_INF_F;
            float mb0 = CUDART_INF_F, mb1 = CUDART_INF_F;
#pragma unroll 8
            for (int p = c * 64; p < (c + 1) * 64; ++p) {
                ulonglong2 xy = tXY[p], zn = tZN[p];
                unsigned long long kA = fma2(az, zn.x, fma2(ay, xy.y, fma2(ax, xy.x, zn.y)));
                unsigned long long kB = fma2(bz, zn.x, fma2(by, xy.y, fma2(bx, xy.x, zn.y)));
                float lo, hi;
                unpackf2(kA, lo, hi); ma0 = fminf(ma0, lo); ma1 = fminf(ma1, hi);
                unpackf2(kB, lo, hi); mb0 = fminf(mb0, lo); mb1 = fminf(mb1, hi);
            }
            const int ch = part * 2 + c;
            g_cmin[ch * N_PRE + i0] = fminf(ma0, ma1);
            g_cmin[ch * N_PRE + i1] = fminf(mb0, mb1);
        }
    }
}

// ---------------------------------------------------------------------------
// Launch 2 (combo, warp-per-query):
//  blocks [0, 2048):  k1 argmin recovery — min over 32 partition minima, owner
//    = lowest partition with pmin==gmin, rescan its 256-wide tile for the first
//    bitwise-equal key -> g_cur2pre (== argmin lowest-index tie rule).
//  blocks [2048, 3072): T = 8th-smallest of 128 chunk minima (exact superset).
// ---------------------------------------------------------------------------
__global__ __launch_bounds__(NTHREADS)
void k_combo(const float* __restrict__ pre, const float* __restrict__ cur) {
    const int w    = threadIdx.x >> 5;
    const int lane = threadIdx.x & 31;

    if (blockIdx.x < N_CUR / FWARPS) {
        const int j = blockIdx.x * FWARPS + w;          // cur query
        const float pm = g_p1_min[lane * N_CUR + j];
        float gm = pm;
#pragma unroll
        for (int off = 16; off > 0; off >>= 1)
            gm = fminf(gm, __shfl_xor_sync(0xFFFFFFFFu, gm, off));
        const unsigned owners = __ballot_sync(0xFFFFFFFFu, pm == gm);
        const int opart = __ffs(owners) - 1;

        const float m2x = -2.0f * cur[j];
        const float m2y = -2.0f * cur[N_CUR + j];
        const float m2z = -2.0f * cur[2 * N_CUR + j];
        const int base = opart * TILE1;
        int found = -1;
#pragma unroll
        for (int t = 0; t < TILE1; t += 32) {
            if (found >= 0) break;                      // uniform
            const float4 c = g_prep[base + t + lane];
            const float key = fmaf(m2z, c.z, fmaf(m2y, c.y, fmaf(m2x, c.x, c.w)));
            unsigned m = __ballot_sync(0xFFFFFFFFu, key == gm);
            if (m) found = base + t + (__ffs(m) - 1);
        }
        if (lane == 0) g_cur2pre[j] = found;
    } else {
        const int i = (blockIdx.x - N_CUR / FWARPS) * FWARPS + w;   // pre query
        float v0 = g_cmin[lane * N_PRE + i];
        float v1 = g_cmin[(lane + 32) * N_PRE + i];
        float v2 = g_cmin[(lane + 64) * N_PRE + i];
        float v3 = g_cmin[(lane + 96) * N_PRE + i];
        float T = 0.0f;
#pragma unroll
        for (int r = 0; r < KNN; ++r) {
            float lmin = fminf(fminf(v0, v1), fminf(v2, v3));
            float gm = lmin;
#pragma unroll
            for (int off = 16; off > 0; off >>= 1)
                gm = fminf(gm, __shfl_xor_sync(0xFFFFFFFFu, gm, off));
            T = gm;
            const unsigned own = __ballot_sync(0xFFFFFFFFu, lmin == gm);
            if (lane == __ffs(own) - 1) {               // remove ONE instance
                if      (v0 == gm) v0 = CUDART_INF_F;
                else if (v1 == gm) v1 = CUDART_INF_F;
                else if (v2 == gm) v2 = CUDART_INF_F;
                else               v3 = CUDART_INF_F;
            }
        }
        if (lane == 0) g_T[i] = T;
    }
}

// ---------------------------------------------------------------------------
// Launch 3: filter + final, warp per pre query. Scan ONLY chunks with min<=T
// (generically exactly 8 of 128 -> 1024 candidates); admit key<=T via
// ballot/popc into smem; exact top-8 via lexicographic warp-argmin; epilogue.
// ---------------------------------------------------------------------------
__global__ __launch_bounds__(NTHREADS)
void k_filter_final(const float* __restrict__ pre, const float* __restrict__ ups,
                    float* __restrict__ out) {
    __shared__ float sk[FWARPS][CAP];
    __shared__ int   si[FWARPS][CAP];
    const int w    = threadIdx.x >> 5;
    const int lane = threadIdx.x & 31;
    const int i    = blockIdx.x * FWARPS + w;

    const float m2x = -2.0f * pre[i];
    const float m2y = -2.0f * pre[N_PRE + i];
    const float m2z = -2.0f * pre[2 * N_PRE + i];
    const float T   = g_T[i];

    unsigned cm[4];
#pragma unroll
    for (int s = 0; s < 4; ++s) {
        const float q = g_cmin[(s * 32 + lane) * N_PRE + i];
        cm[s] = __ballot_sync(0xFFFFFFFFu, q <= T);
    }

    int cnt = 0;
#pragma unroll
    for (int s = 0; s < 4; ++s) {
        unsigned msk = cm[s];
        while (msk) {
            const int p = __ffs(msk) - 1;
            msk &= msk - 1;
            const int base = (s * 32 + p) * CHUNK;
#pragma unroll
            for (int t = 0; t < CHUNK; t += 32) {
                const float4 c = g_curp[base + t + lane];
                const float key = fmaf(m2z, c.z, fmaf(m2y, c.y, fmaf(m2x, c.x, c.w)));
                const bool adm = (key <= T);
                unsigned m = __ballot_sync(0xFFFFFFFFu, adm);
                if (m) {
                    int pos = cnt + __popc(m & ((1u << lane) - 1u));
                    if (adm && pos < CAP) { sk[w][pos] = key; si[w][pos] = base + t + lane; }
                    cnt += __popc(m);
                }
            }
        }
    }
    cnt = min(cnt, CAP);

    float c0 = (lane < cnt)      ? sk[w][lane]      : CUDART_INF_F;
    int   x0 = (lane < cnt)      ? si[w][lane]      : 0x7FFFFFFF;
    float c1 = (lane + 32 < cnt) ? sk[w][lane + 32] : CUDART_INF_F;
    int   x1 = (lane + 32 < cnt) ? si[w][lane + 32] : 0x7FFFFFFF;

    int   sel  = 0;
    float selk = CUDART_INF_F;
#pragma unroll
    for (int r = 0; r < KNN; ++r) {
        float mk = c0; int mi = x0;
        if (c1 < mk || (c1 == mk && x1 < mi)) { mk = c1; mi = x1; }
#pragma unroll
        for (int off = 16; off > 0; off >>= 1) {
            float ok = __shfl_down_sync(0xFFFFFFFFu, mk, off);
            int   oi = __shfl_down_sync(0xFFFFFFFFu, mi, off);
            if (ok < mk || (ok == mk && oi < mi)) { mk = ok; mi = oi; }
        }
        const int   wi = __shfl_sync(0xFFFFFFFFu, mi, 0);
        const float wk = __shfl_sync(0xFFFFFFFFu, mk, 0);
        if (lane == r) { sel = wi; selk = wk; }
        if (x0 == wi) c0 = CUDART_INF_F;
        if (x1 == wi) c1 = CUDART_INF_F;
    }

    const float px = pre[i];
    const float py = pre[N_PRE + i];
    const float pz = pre[2 * N_PRE + i];

    float val = 0.0f;
    if (lane < KNN && selk < CUDART_INF_F) {
        const int j = sel;
        const float4 c = g_curp[j];
        float dx = c.x - px, dy = c.y - py, dz = c.z - pz;
        float dist = sqrtf(fmaf(dz, dz, fmaf(dy, dy, dx * dx)));
        val = (g_cur2pre[j] == i) ? dist : 0.0f;
    }
#pragma unroll
    for (int off = 4; off > 0; off >>= 1)
        val += __shfl_down_sync(0xFFFFFFFFu, val, off);

    if (lane == 0) out[i] = val / ups[i];
}

// ---------------------------------------------------------------------------
extern "C" void kernel_launch(void* const* d_in, const int* in_sizes, int n_in,
                              void* d_out, int out_size) {
    const float* pre = (const float*)d_in[0];   // (1, 3, 8192)
    const float* cur = (const float*)d_in[1];   // (1, 3, 16384)
    const float* ups = (const float*)d_in[2];   // (1, 8192)
    float* out = (float*)d_out;                 // (1, 8192)

    k_minpass<<<K1BLK + K2BLK, NTHREADS>>>(pre, cur);              // 2048 blocks

    k_combo<<<N_CUR / FWARPS + N_PRE / FWARPS, NTHREADS>>>(pre, cur);

    k_filter_final<<<N_PRE / FWARPS, NTHREADS>>>(pre, ups, out);
}

// round 11
// speedup vs baseline: 1.1228x; 1.0120x over previous
#include <cuda_runtime.h>
#include <math_constants.h>

#define N_PRE 8192
#define N_CUR 16384
#define KNN   8
#define NTHREADS 256

#define P1    32                  // partitions over pre (k1)
#define TILE1 (N_PRE / P1)        // 256
#define P2    64                  // partitions over cur (k2), 256 wide
#define TILE2 (N_CUR / P2)        // 256
#define NCHUNK 128                // fine chunks over cur (128 wide)
#define CHUNK  (N_CUR / NCHUNK)   // 128
#define CAP   64
#define FWARPS 8
#define QB    4                   // queries per thread in min passes
#define K1BLK (P1 * (N_CUR / (NTHREADS * QB)))   // 32*16 = 512
#define K2BLK (P2 * (N_PRE / (NTHREADS * QB)))   // 64*8  = 512

// Scratch (device globals; no allocations allowed)
__device__ int    g_cur2pre[N_CUR];
__device__ float  g_p1_min[P1 * N_CUR];    // per-partition min key (cur->pre)
__device__ float  g_cmin[NCHUNK * N_PRE];  // per-128-chunk min key (pre->cur)
__device__ float  g_T[N_PRE];
__device__ float4 g_prep[N_PRE];           // packed pre: (x,y,z,|p|^2)
__device__ float4 g_curp[N_CUR];           // packed cur: (x,y,z,|c|^2)

// ---- packed f32x2 helpers ---------------------------------------------------
__device__ __forceinline__ unsigned long long packf2(float a, float b) {
    unsigned long long r;
    asm("mov.b64 %0, {%1,%2};" : "=l"(r) : "f"(a), "f"(b));
    return r;
}
__device__ __forceinline__ unsigned long long fma2(unsigned long long a,
                                                   unsigned long long b,
                                                   unsigned long long c) {
    unsigned long long d;
    asm("fma.rn.f32x2 %0, %1, %2, %3;" : "=l"(d) : "l"(a), "l"(b), "l"(c));
    return d;
}
__device__ __forceinline__ void unpackf2(unsigned long long v, float& lo, float& hi) {
    asm("mov.b64 {%0,%1}, %2;" : "=f"(lo), "=f"(hi) : "l"(v));
}

// key(q, c) = fmaf(m2z, cz, fmaf(m2y, cy, fmaf(m2x, cx, |c|^2))), m2* = -2*q*.
// Per-lane IEEE fma order identical in packed and scalar recompute -> bitwise
// equal across kernels.

// ---------------------------------------------------------------------------
// Launch 1: merged index-free min passes. 1024 uniform blocks, 128-iter
// mainloops, 4 queries per thread (2 LDS amortized over 8 pairs/thread/iter).
//  blocks [0, 512):    k1 — min over a 256-wide PRE tile for 1024 cur queries
//  blocks [512, 1024): k2 — two 128-chunk minima over a 256-wide CUR tile for
//                      1024 pre queries
// ---------------------------------------------------------------------------
__global__ __launch_bounds__(NTHREADS, 5)
void k_minpass(const float* __restrict__ pre, const float* __restrict__ cur) {
    __shared__ ulonglong2 tXY[128], tZN[128];
    const int tid = threadIdx.x;
    const int bid = blockIdx.x;

    if (bid < K1BLK) {
        // ---------------- k1: cur -> pre partition minima ----------------
        const int part = bid & (P1 - 1);
        const int yq   = bid >> 5;                    // 0..15
        const int base = part * TILE1;
        if (tid < TILE1 / 2) {
            int t0 = base + 2 * tid, t1 = t0 + 1;
            float x0 = pre[t0],             x1 = pre[t1];
            float y0 = pre[N_PRE + t0],     y1 = pre[N_PRE + t1];
            float z0 = pre[2 * N_PRE + t0], z1 = pre[2 * N_PRE + t1];
            float n0 = fmaf(z0, z0, fmaf(y0, y0, x0 * x0));
            float n1 = fmaf(z1, z1, fmaf(y1, y1, x1 * x1));
            tXY[tid] = make_ulonglong2(packf2(x0, x1), packf2(y0, y1));
            tZN[tid] = make_ulonglong2(packf2(z0, z1), packf2(n0, n1));
            if (yq == 0) {
                g_prep[t0] = make_float4(x0, y0, z0, n0);
                g_prep[t1] = make_float4(x1, y1, z1, n1);
            }
        }
        __syncthreads();

        unsigned long long qx[QB], qy[QB], qz[QB];
        int j[QB];
#pragma unroll
        for (int q = 0; q < QB; ++q) {
            j[q] = yq * (NTHREADS * QB) + q * NTHREADS + tid;
            float vx = -2.0f * cur[j[q]];
            float vy = -2.0f * cur[N_CUR + j[q]];
            float vz = -2.0f * cur[2 * N_CUR + j[q]];
            qx[q] = packf2(vx, vx); qy[q] = packf2(vy, vy); qz[q] = packf2(vz, vz);
        }

        float m0[QB], m1[QB];
#pragma unroll
        for (int q = 0; q < QB; ++q) { m0[q] = CUDART_INF_F; m1[q] = CUDART_INF_F; }

#pragma unroll 4
        for (int p = 0; p < TILE1 / 2; ++p) {
            const ulonglong2 xy = tXY[p], zn = tZN[p];
#pragma unroll
            for (int q = 0; q < QB; ++q) {
                unsigned long long k = fma2(qz[q], zn.x, fma2(qy[q], xy.y, fma2(qx[q], xy.x, zn.y)));
                float lo, hi;
                unpackf2(k, lo, hi);
                m0[q] = fminf(m0[q], lo);
                m1[q] = fminf(m1[q], hi);
            }
        }
#pragma unroll
        for (int q = 0; q < QB; ++q)
            g_p1_min[part * N_CUR + j[q]] = fminf(m0[q], m1[q]);
    } else {
        // ---------------- k2: pre -> cur 128-chunk minima ----------------
        const int b    = bid - K1BLK;
        const int part = b & (P2 - 1);
        const int yq   = b >> 6;                      // 0..7
        const int base = part * TILE2;
        if (tid < TILE2 / 2) {
            int t0 = base + 2 * tid, t1 = t0 + 1;
            float x0 = cur[t0],             x1 = cur[t1];
            float y0 = cur[N_CUR + t0],     y1 = cur[N_CUR + t1];
            float z0 = cur[2 * N_CUR + t0], z1 = cur[2 * N_CUR + t1];
            float n0 = fmaf(z0, z0, fmaf(y0, y0, x0 * x0));
            float n1 = fmaf(z1, z1, fmaf(y1, y1, x1 * x1));
            tXY[tid] = make_ulonglong2(packf2(x0, x1), packf2(y0, y1));
            tZN[tid] = make_ulonglong2(packf2(z0, z1), packf2(n0, n1));
            if (yq == 0) {
                g_curp[t0] = make_float4(x0, y0, z0, n0);
                g_curp[t1] = make_float4(x1, y1, z1, n1);
            }
        }
        __syncthreads();

        unsigned long long qx[QB], qy[QB], qz[QB];
        int idx[QB];
#pragma unroll
        for (int q = 0; q < QB; ++q) {
            idx[q] = yq * (NTHREADS * QB) + q * NTHREADS + tid;
            float vx = -2.0f * pre[idx[q]];
            float vy = -2.0f * pre[N_PRE + idx[q]];
            float vz = -2.0f * pre[2 * N_PRE + idx[q]];
            qx[q] = packf2(vx, vx); qy[q] = packf2(vy, vy); qz[q] = packf2(vz, vz);
        }

#pragma unroll
        for (int c = 0; c < 2; ++c) {                 // 2 chunks of 128
            float m0[QB], m1[QB];
#pragma unroll
            for (int q = 0; q < QB; ++q) { m0[q] = CUDART_INF_F; m1[q] = CUDART_INF_F; }
#pragma unroll 4
            for (int p = c * 64; p < (c + 1) * 64; ++p) {
                const ulonglong2 xy = tXY[p], zn = tZN[p];
#pragma unroll
                for (int q = 0; q < QB; ++q) {
                    unsigned long long k = fma2(qz[q], zn.x, fma2(qy[q], xy.y, fma2(qx[q], xy.x, zn.y)));
                    float lo, hi;
                    unpackf2(k, lo, hi);
                    m0[q] = fminf(m0[q], lo);
                    m1[q] = fminf(m1[q], hi);
                }
            }
            const int ch = part * 2 + c;
#pragma unroll
            for (int q = 0; q < QB; ++q)
                g_cmin[ch * N_PRE + idx[q]] = fminf(m0[q], m1[q]);
        }
    }
}

// ---------------------------------------------------------------------------
// Launch 2 (combo, warp-per-query):
//  blocks [0, 2048):  k1 argmin recovery — min over 32 partition minima, owner
//    = lowest partition with pmin==gmin, rescan its 256-wide tile for the first
//    bitwise-equal key -> g_cur2pre (== argmin lowest-index tie rule).
//  blocks [2048, 3072): T = 8th-smallest of 128 chunk minima (exact superset).
// ---------------------------------------------------------------------------
__global__ __launch_bounds__(NTHREADS)
void k_combo(const float* __restrict__ pre, const float* __restrict__ cur) {
    const int w    = threadIdx.x >> 5;
    const int lane = threadIdx.x & 31;

    if (blockIdx.x < N_CUR / FWARPS) {
        const int j = blockIdx.x * FWARPS + w;          // cur query
        const float pm = g_p1_min[lane * N_CUR + j];
        float gm = pm;
#pragma unroll
        for (int off = 16; off > 0; off >>= 1)
            gm = fminf(gm, __shfl_xor_sync(0xFFFFFFFFu, gm, off));
        const unsigned owners = __ballot_sync(0xFFFFFFFFu, pm == gm);
        const int opart = __ffs(owners) - 1;

        const float m2x = -2.0f * cur[j];
        const float m2y = -2.0f * cur[N_CUR + j];
        const float m2z = -2.0f * cur[2 * N_CUR + j];
        const int base = opart * TILE1;
        int found = -1;
#pragma unroll
        for (int t = 0; t < TILE1; t += 32) {
            if (found >= 0) break;                      // uniform
            const float4 c = g_prep[base + t + lane];
            const float key = fmaf(m2z, c.z, fmaf(m2y, c.y, fmaf(m2x, c.x, c.w)));
            unsigned m = __ballot_sync(0xFFFFFFFFu, key == gm);
            if (m) found = base + t + (__ffs(m) - 1);
        }
        if (lane == 0) g_cur2pre[j] = found;
    } else {
        const int i = (blockIdx.x - N_CUR / FWARPS) * FWARPS + w;   // pre query
        float v0 = g_cmin[lane * N_PRE + i];
        float v1 = g_cmin[(lane + 32) * N_PRE + i];
        float v2 = g_cmin[(lane + 64) * N_PRE + i];
        float v3 = g_cmin[(lane + 96) * N_PRE + i];
        float T = 0.0f;
#pragma unroll
        for (int r = 0; r < KNN; ++r) {
            float lmin = fminf(fminf(v0, v1), fminf(v2, v3));
            float gm = lmin;
#pragma unroll
            for (int off = 16; off > 0; off >>= 1)
                gm = fminf(gm, __shfl_xor_sync(0xFFFFFFFFu, gm, off));
            T = gm;
            const unsigned own = __ballot_sync(0xFFFFFFFFu, lmin == gm);
            if (lane == __ffs(own) - 1) {               // remove ONE instance
                if      (v0 == gm) v0 = CUDART_INF_F;
                else if (v1 == gm) v1 = CUDART_INF_F;
                else if (v2 == gm) v2 = CUDART_INF_F;
                else               v3 = CUDART_INF_F;
            }
        }
        if (lane == 0) g_T[i] = T;
    }
}

// ---------------------------------------------------------------------------
// Launch 3: filter + final, warp per pre query. Scan ONLY chunks with min<=T
// (generically exactly 8 of 128 -> 1024 candidates); admit key<=T via
// ballot/popc into smem; exact top-8 via lexicographic warp-argmin; epilogue.
// ---------------------------------------------------------------------------
__global__ __launch_bounds__(NTHREADS)
void k_filter_final(const float* __restrict__ pre, const float* __restrict__ ups,
                    float* __restrict__ out) {
    __shared__ float sk[FWARPS][CAP];
    __shared__ int   si[FWARPS][CAP];
    const int w    = threadIdx.x >> 5;
    const int lane = threadIdx.x & 31;
    const int i    = blockIdx.x * FWARPS + w;

    const float m2x = -2.0f * pre[i];
    const float m2y = -2.0f * pre[N_PRE + i];
    const float m2z = -2.0f * pre[2 * N_PRE + i];
    const float T   = g_T[i];

    unsigned cm[4];
#pragma unroll
    for (int s = 0; s < 4; ++s) {
        const float q = g_cmin[(s * 32 + lane) * N_PRE + i];
        cm[s] = __ballot_sync(0xFFFFFFFFu, q <= T);
    }

    int cnt = 0;
#pragma unroll
    for (int s = 0; s < 4; ++s) {
        unsigned msk = cm[s];
        while (msk) {
            const int p = __ffs(msk) - 1;
            msk &= msk - 1;
            const int base = (s * 32 + p) * CHUNK;
#pragma unroll
            for (int t = 0; t < CHUNK; t += 32) {
                const float4 c = g_curp[base + t + lane];
                const float key = fmaf(m2z, c.z, fmaf(m2y, c.y, fmaf(m2x, c.x, c.w)));
                const bool adm = (key <= T);
                unsigned m = __ballot_sync(0xFFFFFFFFu, adm);
                if (m) {
                    int pos = cnt + __popc(m & ((1u << lane) - 1u));
                    if (adm && pos < CAP) { sk[w][pos] = key; si[w][pos] = base + t + lane; }
                    cnt += __popc(m);
                }
            }
        }
    }
    cnt = min(cnt, CAP);

    float c0 = (lane < cnt)      ? sk[w][lane]      : CUDART_INF_F;
    int   x0 = (lane < cnt)      ? si[w][lane]      : 0x7FFFFFFF;
    float c1 = (lane + 32 < cnt) ? sk[w][lane + 32] : CUDART_INF_F;
    int   x1 = (lane + 32 < cnt) ? si[w][lane + 32] : 0x7FFFFFFF;

    int   sel  = 0;
    float selk = CUDART_INF_F;
#pragma unroll
    for (int r = 0; r < KNN; ++r) {
        float mk = c0; int mi = x0;
        if (c1 < mk || (c1 == mk && x1 < mi)) { mk = c1; mi = x1; }
#pragma unroll
        for (int off = 16; off > 0; off >>= 1) {
            float ok = __shfl_down_sync(0xFFFFFFFFu, mk, off);
            int   oi = __shfl_down_sync(0xFFFFFFFFu, mi, off);
            if (ok < mk || (ok == mk && oi < mi)) { mk = ok; mi = oi; }
        }
        const int   wi = __shfl_sync(0xFFFFFFFFu, mi, 0);
        const float wk = __shfl_sync(0xFFFFFFFFu, mk, 0);
        if (lane == r) { sel = wi; selk = wk; }
        if (x0 == wi) c0 = CUDART_INF_F;
        if (x1 == wi) c1 = CUDART_INF_F;
    }

    const float px = pre[i];
    const float py = pre[N_PRE + i];
    const float pz = pre[2 * N_PRE + i];

    float val = 0.0f;
    if (lane < KNN && selk < CUDART_INF_F) {
        const int j = sel;
        const float4 c = g_curp[j];
        float dx = c.x - px, dy = c.y - py, dz = c.z - pz;
        float dist = sqrtf(fmaf(dz, dz, fmaf(dy, dy, dx * dx)));
        val = (g_cur2pre[j] == i) ? dist : 0.0f;
    }
#pragma unroll
    for (int off = 4; off > 0; off >>= 1)
        val += __shfl_down_sync(0xFFFFFFFFu, val, off);

    if (lane == 0) out[i] = val / ups[i];
}

// ---------------------------------------------------------------------------
extern "C" void kernel_launch(void* const* d_in, const int* in_sizes, int n_in,
                              void* d_out, int out_size) {
    const float* pre = (const float*)d_in[0];   // (1, 3, 8192)
    const float* cur = (const float*)d_in[1];   // (1, 3, 16384)
    const float* ups = (const float*)d_in[2];   // (1, 8192)
    float* out = (float*)d_out;                 // (1, 8192)

    k_minpass<<<K1BLK + K2BLK, NTHREADS>>>(pre, cur);              // 1024 blocks

    k_combo<<<N_CUR / FWARPS + N_PRE / FWARPS, NTHREADS>>>(pre, cur);

    k_filter_final<<<N_PRE / FWARPS, NTHREADS>>>(pre, ups, out);
}